// round 4
// baseline (speedup 1.0000x reference)
#include <cuda_runtime.h>
#include <math.h>

// Accumulators (no allocations allowed; device globals, zero-initialized).
__device__ double g_sum;          // masked pair-loss sum
__device__ unsigned int g_tick;   // block completion counter (self-wrapping)

constexpr int TILE    = 512;   // square tile edge
constexpr int THREADS = 256;   // threads per block (2 i-rows per thread)

// ---------------------------------------------------------------------------
// Single fused kernel, triangle-tiled 512x512, 2 i-rows/thread:
//   * distances computed in-block from pv/pt (no prep kernel)
//   * for each unordered pair {i,j} exactly one direction is masked-in
//     (ties negligible for fp32 normal data): add relu of the direction
//     whose d^2 is smaller (sqrt is monotone -> compare d^2)
//   * last-finishing block writes out[0] (no epilogue kernel)
// ---------------------------------------------------------------------------
__global__ __launch_bounds__(THREADS) void fused_kernel(
    const float* __restrict__ energies,
    const float* __restrict__ pv,
    const float* __restrict__ pt,
    int B, int P, int T, int NB, double invcnt,
    float* __restrict__ out)
{
    // --- triangle decode: bid -> (ti, tj), ti <= tj (T is small) ---
    int bid = blockIdx.x;
    int ti = 0, rem = bid;
    while (rem >= T - ti) { rem -= (T - ti); ti++; }
    int tj = ti + rem;

    __shared__ float2 jt[TILE];            // j tile {d^2, e}
    __shared__ float  ssum[THREADS / 32];

    const float NANF = __int_as_float(0x7FC00000);
    int t = threadIdx.x;

    // --- in-block prep: {d^2, e} for one row ---
    auto row_de = [&](int row) -> float2 {
        if (row >= B) return make_float2(0.0f, NANF);   // NaN e -> relu()=0
        float s = 0.0f;
        if (P == 16) {
            const float4* pv4 = (const float4*)(pv + (size_t)row * 16);
            const float4* pt4 = (const float4*)pt;
            #pragma unroll
            for (int q = 0; q < 4; q++) {
                float4 v = pv4[q];
                float4 w = pt4[q];
                float a = v.x - w.x, b = v.y - w.y;
                float c = v.z - w.z, d = v.w - w.w;
                s = fmaf(a, a, fmaf(b, b, fmaf(c, c, fmaf(d, d, s))));
            }
        } else {
            for (int p = 0; p < P; p++) {
                float df = pv[(size_t)row * P + p] - pt[p];
                s = fmaf(df, df, s);
            }
        }
        return make_float2(s, energies[row]);
    };

    // my two i rows (registers)
    float2 mi0 = row_de(ti * TILE + t);
    float2 mi1 = row_de(ti * TILE + t + THREADS);

    // j tile (shared); diagonal reuses the i rows
    if (ti == tj) {
        jt[t]           = mi0;
        jt[t + THREADS] = mi1;
    } else {
        jt[t]           = row_de(tj * TILE + t);
        jt[t + THREADS] = row_de(tj * TILE + t + THREADS);
    }

    float d0 = mi0.x, a0 = mi0.y + 1.0f, b0 = 1.0f - mi0.y;
    float d1 = mi1.x, a1 = mi1.y + 1.0f, b1 = 1.0f - mi1.y;
    // invalid i row: e is NaN -> a,b NaN -> all relu contributions 0

    __syncthreads();

    float acc00 = 0.0f, acc01 = 0.0f, acc10 = 0.0f, acc11 = 0.0f;
    const float4* jt4 = (const float4*)jt;   // {d_j0, e_j0, d_j1, e_j1}

    if (ti != tj) {
        #pragma unroll 4
        for (int j2 = 0; j2 < TILE / 2; j2++) {
            float4 p = jt4[j2];              // one LDS.128 -> 4 pairs
            float v00 = (d0 < p.x) ? (a0 - p.y) : (b0 + p.y);
            float v01 = (d0 < p.z) ? (a0 - p.w) : (b0 + p.w);
            float v10 = (d1 < p.x) ? (a1 - p.y) : (b1 + p.y);
            float v11 = (d1 < p.z) ? (a1 - p.w) : (b1 + p.w);
            acc00 += fmaxf(v00, 0.0f);
            acc01 += fmaxf(v01, 0.0f);
            acc10 += fmaxf(v10, 0.0f);
            acc11 += fmaxf(v11, 0.0f);
        }
    } else {
        // diagonal tile: count only local j > local i (each pair once)
        int i0l = t, i1l = t + THREADS;
        #pragma unroll 4
        for (int j2 = 0; j2 < TILE / 2; j2++) {
            float4 p = jt4[j2];
            int j0 = 2 * j2, j1 = 2 * j2 + 1;
            float v00 = (d0 < p.x) ? (a0 - p.y) : (b0 + p.y);
            float v01 = (d0 < p.z) ? (a0 - p.w) : (b0 + p.w);
            float v10 = (d1 < p.x) ? (a1 - p.y) : (b1 + p.y);
            float v11 = (d1 < p.z) ? (a1 - p.w) : (b1 + p.w);
            if (j0 > i0l) acc00 += fmaxf(v00, 0.0f);
            if (j1 > i0l) acc01 += fmaxf(v01, 0.0f);
            if (j0 > i1l) acc10 += fmaxf(v10, 0.0f);
            if (j1 > i1l) acc11 += fmaxf(v11, 0.0f);
        }
    }

    float acc = (acc00 + acc01) + (acc10 + acc11);

    // --- block reduction ---
    #pragma unroll
    for (int o = 16; o > 0; o >>= 1)
        acc += __shfl_down_sync(0xFFFFFFFFu, acc, o);

    int w = t >> 5, l = t & 31;
    if (l == 0) ssum[w] = acc;
    __syncthreads();

    // --- global accumulation + last-block epilogue ---
    if (t == 0) {
        float a = 0.0f;
        #pragma unroll
        for (int k = 0; k < THREADS / 32; k++) a += ssum[k];
        atomicAdd(&g_sum, (double)a);
        __threadfence();
        // atomicInc wraps to 0 at NB-1 -> self-resetting, graph-replayable
        unsigned int old = atomicInc(&g_tick, (unsigned int)(NB - 1));
        if (old == (unsigned int)(NB - 1)) {
            unsigned long long bits =
                atomicExch((unsigned long long*)&g_sum, 0ull); // read + reset
            out[0] = (float)(__longlong_as_double(bits) * invcnt);
        }
    }
}

// ---------------------------------------------------------------------------
extern "C" void kernel_launch(void* const* d_in, const int* in_sizes, int n_in,
                              void* d_out, int out_size) {
    const float* energies = (const float*)d_in[0];   // (B, 1)
    const float* pv       = (const float*)d_in[1];   // (B, P)
    const float* pt       = (const float*)d_in[2];   // (P,)
    float* out            = (float*)d_out;

    int B = in_sizes[0];
    int P = in_sizes[2];

    int T  = (B + TILE - 1) / TILE;
    int NB = T * (T + 1) / 2;

    double cnt = (double)B * (double)(B - 1) * 0.5;
    if (cnt < 1.0) cnt = 1.0;

    fused_kernel<<<NB, THREADS>>>(energies, pv, pt, B, P, T, NB, 1.0 / cnt, out);
}